// round 16
// baseline (speedup 1.0000x reference)
#include <cuda_runtime.h>
#include <cuda_bf16.h>
#include <math.h>
#include <stdint.h>

#define N_NODES 50000
#define E_RAW   800000
#define E_TOT   (E_RAW + N_NODES)
#define SCAN_BLOCKS 196   // 196*256 = 50176 >= 50000

// ---------------- scratch (device globals; no allocation in kernel_launch) ----
__device__ __align__(16) __nv_bfloat16 g_h1b[N_NODES * 256];   // x @ W1 (bf16)
__device__ __align__(16) __nv_bfloat16 g_w1hl[8 * 256 * 64];   // W1 split, chunk-major
__device__ __align__(16) float g_asrc1[N_NODES * 4];
__device__ __align__(16) float g_adst1[N_NODES * 4];
__device__ __align__(16) float g_h2[N_NODES * 16];
__device__ float g_asrc2[N_NODES];
__device__ float g_adst2[N_NODES];
__device__ int   g_deg[N_NODES];
__device__ int   g_off[N_NODES + 1];
__device__ int   g_cur[N_NODES];
__device__ int   g_csr[E_TOT];
__device__ int   g_is64;
__device__ int   g_bsum[SCAN_BLOCKS];
__device__ int   g_boff[SCAN_BLOCKS];

// ---------------- host-side stream/events for capture-time fork/join --------
static cudaStream_t g_s2;
static cudaEvent_t  g_evFork, g_evJoin;
namespace {
struct _StreamInit {
    _StreamInit() {
        cudaStreamCreateWithFlags(&g_s2, cudaStreamNonBlocking);
        cudaEventCreateWithFlags(&g_evFork, cudaEventDisableTiming);
        cudaEventCreateWithFlags(&g_evJoin, cudaEventDisableTiming);
    }
};
_StreamInit _stream_init;
}

// ---------------- warp reductions ----------------
__device__ __forceinline__ float warp_max(float v) {
#pragma unroll
    for (int o = 16; o > 0; o >>= 1) v = fmaxf(v, __shfl_xor_sync(0xffffffffu, v, o));
    return v;
}
__device__ __forceinline__ float warp_sum(float v) {
#pragma unroll
    for (int o = 16; o > 0; o >>= 1) v += __shfl_xor_sync(0xffffffffu, v, o);
    return v;
}

// ---------------- detect edge dtype + init degrees (merged) ----------------
__global__ void detect_init_kernel(const void* __restrict__ eiv) {
    __shared__ int bad;
    int i = blockIdx.x * 256 + threadIdx.x;
    if (i < N_NODES) g_deg[i] = 1;  // self loop
    if (blockIdx.x == 0) {
        if (threadIdx.x == 0) bad = 0;
        __syncthreads();
        const long long* p = (const long long*)eiv;
        long long v = p[threadIdx.x];
        if (v < 0 || v >= (long long)N_NODES) atomicOr(&bad, 1);
        __syncthreads();
        if (threadIdx.x == 0) g_is64 = bad ? 0 : 1;
    }
}

__device__ __forceinline__ int load_edge(const void* eiv, int idx, int is64) {
    if (is64) return (int)((const long long*)eiv)[idx];
    return ((const int*)eiv)[idx];
}

// ---------------- CSR build ----------------
__global__ void count_kernel(const void* __restrict__ eiv) {
    int i = blockIdx.x * blockDim.x + threadIdx.x;
    if (i < E_RAW) {
        int dst = load_edge(eiv, E_RAW + i, g_is64);
        if ((unsigned)dst < (unsigned)N_NODES) atomicAdd(&g_deg[dst], 1);
    }
}

__global__ void scan1_kernel() {
    __shared__ int wsum[8];
    int idx = blockIdx.x * 256 + threadIdx.x;
    int d = (idx < N_NODES) ? g_deg[idx] : 0;
    int lane = threadIdx.x & 31, wid = threadIdx.x >> 5;
#pragma unroll
    for (int o = 16; o > 0; o >>= 1) d += __shfl_xor_sync(0xffffffffu, d, o);
    if (lane == 0) wsum[wid] = d;
    __syncthreads();
    if (threadIdx.x == 0) {
        int s = 0;
#pragma unroll
        for (int w = 0; w < 8; w++) s += wsum[w];
        g_bsum[blockIdx.x] = s;
    }
}

__global__ void scan2_kernel() {
    __shared__ int woff[8];
    int t = threadIdx.x;
    int v = (t < SCAN_BLOCKS) ? g_bsum[t] : 0;
    int lane = t & 31, wid = t >> 5;
    int s = v;
#pragma unroll
    for (int o = 1; o < 32; o <<= 1) {
        int u = __shfl_up_sync(0xffffffffu, s, o);
        if (lane >= o) s += u;
    }
    if (lane == 31) woff[wid] = s;
    __syncthreads();
    if (t == 0) {
        int run = 0;
#pragma unroll
        for (int w = 0; w < 8; w++) { int x = woff[w]; woff[w] = run; run += x; }
    }
    __syncthreads();
    int excl = s - v + woff[wid];
    if (t < SCAN_BLOCKS) g_boff[t] = excl;
    if (t == SCAN_BLOCKS - 1) g_off[N_NODES] = excl + v;
}

__global__ void scan3_kernel() {
    __shared__ int woff[8];
    int idx = blockIdx.x * 256 + threadIdx.x;
    int v = (idx < N_NODES) ? g_deg[idx] : 0;
    int lane = threadIdx.x & 31, wid = threadIdx.x >> 5;
    int s = v;
#pragma unroll
    for (int o = 1; o < 32; o <<= 1) {
        int u = __shfl_up_sync(0xffffffffu, s, o);
        if (lane >= o) s += u;
    }
    if (lane == 31) woff[wid] = s;
    __syncthreads();
    if (threadIdx.x == 0) {
        int run = 0;
#pragma unroll
        for (int w = 0; w < 8; w++) { int x = woff[w]; woff[w] = run; run += x; }
    }
    __syncthreads();
    int off = s - v + woff[wid] + g_boff[blockIdx.x];
    if (idx < N_NODES) { g_off[idx] = off; g_cur[idx] = off; }
}

__global__ void scatter_kernel(const void* __restrict__ eiv) {
    int i = blockIdx.x * blockDim.x + threadIdx.x;
    if (i < E_RAW) {
        int is64 = g_is64;
        int src = load_edge(eiv, i, is64);
        int dst = load_edge(eiv, E_RAW + i, is64);
        if ((unsigned)src < (unsigned)N_NODES && (unsigned)dst < (unsigned)N_NODES) {
            int pos = atomicAdd(&g_cur[dst], 1);
            if ((unsigned)pos < (unsigned)E_TOT) g_csr[pos] = src;
        }
    } else if (i < E_RAW + N_NODES) {
        int nn = i - E_RAW;
        int pos = atomicAdd(&g_cur[nn], 1);
        if ((unsigned)pos < (unsigned)E_TOT) g_csr[pos] = nn;
    }
}

// ---------------- bf16 helpers ----------------
__device__ __forceinline__ uint32_t pack_bf16x2(float a, float b) {
    __nv_bfloat16 ah = __float2bfloat16(a), bh = __float2bfloat16(b);
    return (uint32_t)__bfloat16_as_ushort(ah) | ((uint32_t)__bfloat16_as_ushort(bh) << 16);
}

// ---------------- pre-convert W1 only: [chunk][n][hi32|lo32] ----------------
__global__ void w1cvt_kernel(const float* __restrict__ W) {
    int idx = blockIdx.x * 256 + threadIdx.x;
    if (idx >= 2048) return;
    int c = idx >> 8, n = idx & 255;
    uint32_t hp[16], lp[16];
#pragma unroll
    for (int j = 0; j < 16; j++) {
        float a = W[(size_t)(c * 32 + 2 * j) * 256 + n];
        float b = W[(size_t)(c * 32 + 2 * j + 1) * 256 + n];
        hp[j] = pack_bf16x2(a, b);
        float la = a - __bfloat162float(__float2bfloat16(a));
        float lb = b - __bfloat162float(__float2bfloat16(b));
        lp[j] = pack_bf16x2(la, lb);
    }
    __nv_bfloat16* dst = g_w1hl + (size_t)(c * 256 + n) * 64;
#pragma unroll
    for (int q = 0; q < 4; q++) {
        *(uint4*)(dst + q * 8)      = make_uint4(hp[4 * q], hp[4 * q + 1], hp[4 * q + 2], hp[4 * q + 3]);
        *(uint4*)(dst + 32 + q * 8) = make_uint4(lp[4 * q], lp[4 * q + 1], lp[4 * q + 2], lp[4 * q + 3]);
    }
}

// ============================================================================
// GEMM1 via warp-level mma.sync (bf16 split), software-pipelined staging:
// store(c) -> sync -> prefetch(c+1) loads in flight -> MMA(c) -> sync.
// ============================================================================
#define G1_LDS 72   // smem row stride in bf16

__device__ __forceinline__ uint32_t smem_u32(const void* p) {
    uint32_t a;
    asm("{ .reg .u64 t; cvta.to.shared.u64 t, %1; cvt.u32.u64 %0, t; }" : "=r"(a) : "l"(p));
    return a;
}
__device__ __forceinline__ void ldsm4(uint32_t* r, uint32_t addr) {
    asm volatile("ldmatrix.sync.aligned.m8n8.x4.shared.b16 {%0,%1,%2,%3}, [%4];"
                 : "=r"(r[0]), "=r"(r[1]), "=r"(r[2]), "=r"(r[3]) : "r"(addr));
}
__device__ __forceinline__ void mma_bf16(float* d, const uint32_t* a, const uint32_t* b) {
    asm volatile(
        "mma.sync.aligned.m16n8k16.row.col.f32.bf16.bf16.f32 "
        "{%0,%1,%2,%3}, {%4,%5,%6,%7}, {%8,%9}, {%0,%1,%2,%3};"
        : "+f"(d[0]), "+f"(d[1]), "+f"(d[2]), "+f"(d[3])
        : "r"(a[0]), "r"(a[1]), "r"(a[2]), "r"(a[3]), "r"(b[0]), "r"(b[1]));
}

__global__ __launch_bounds__(256)
void gemm1_mma_kernel(const float* __restrict__ x,
                      const float* __restrict__ attS, const float* __restrict__ attD) {
    __shared__ __align__(16) __nv_bfloat16 As[128 * G1_LDS];
    __shared__ __align__(16) __nv_bfloat16 Bs[128 * G1_LDS];
    __shared__ float sS[256], sD[256];

    int tid = threadIdx.x, wid = tid >> 5, lane = tid & 31;
    int wr = wid >> 1, wc = wid & 1;          // warp grid 4x2
    int tile0 = blockIdx.y * 128;             // row base
    int cn = blockIdx.x * 128;                // col base
    sS[tid] = attS[tid];
    sD[tid] = attD[tid];

    float acc[2][8][4];
#pragma unroll
    for (int m = 0; m < 2; m++)
#pragma unroll
        for (int nf = 0; nf < 8; nf++)
#pragma unroll
            for (int j = 0; j < 4; j++) acc[m][nf][j] = 0.f;

    uint32_t sA = smem_u32(As), sB = smem_u32(Bs);
    int raA = lane & 15, kaA = (lane >> 4) * 8;                 // A: x4 = m16 x k16
    int nB = (lane & 7) | ((lane >> 4) << 3);                   // B: x4 = n16 x k16
    int kB = (lane & 8) ? 8 : 0;

    // per-thread staging coordinates (same for every chunk)
    int rowA = tid >> 3, gA = tid & 7;        // used with it-offset below
    (void)rowA; (void)gA;

    float4 rA[4];
    uint4  rB[4];

    // ---- prefetch chunk 0 ----
#pragma unroll
    for (int it = 0; it < 4; it++) {
        int idx = tid + it * 256;
        int row = idx >> 3, g = idx & 7;
        int grow = tile0 + row;
        rA[it] = make_float4(0.f, 0.f, 0.f, 0.f);
        if (grow < N_NODES) rA[it] = *(const float4*)&x[(size_t)grow * 256 + 0 * 32 + g * 4];
        int nl = idx >> 3, q = idx & 7;
        rB[it] = *(const uint4*)&g_w1hl[(size_t)(0 * 256 + cn + nl) * 64 + q * 8];
    }

    for (int c = 0; c < 8; c++) {
        // ---- store staged regs to smem (convert A on the fly) ----
#pragma unroll
        for (int it = 0; it < 4; it++) {
            int idx = tid + it * 256;
            int row = idx >> 3, g = idx & 7;
            float4 v = rA[it];
            uint32_t hi0 = pack_bf16x2(v.x, v.y), hi1 = pack_bf16x2(v.z, v.w);
            float l0 = v.x - __bfloat162float(__float2bfloat16(v.x));
            float l1 = v.y - __bfloat162float(__float2bfloat16(v.y));
            float l2 = v.z - __bfloat162float(__float2bfloat16(v.z));
            float l3 = v.w - __bfloat162float(__float2bfloat16(v.w));
            uint32_t lo0 = pack_bf16x2(l0, l1), lo1 = pack_bf16x2(l2, l3);
            *(uint2*)&As[row * G1_LDS + g * 4]      = make_uint2(hi0, hi1);
            *(uint2*)&As[row * G1_LDS + 32 + g * 4] = make_uint2(lo0, lo1);
            *(uint4*)&Bs[row * G1_LDS + g * 8]      = rB[it];
        }
        __syncthreads();

        // ---- issue prefetch for chunk c+1 (rides under the MMAs) ----
        if (c < 7) {
            int kb = (c + 1) * 32;
#pragma unroll
            for (int it = 0; it < 4; it++) {
                int idx = tid + it * 256;
                int row = idx >> 3, g = idx & 7;
                int grow = tile0 + row;
                rA[it] = make_float4(0.f, 0.f, 0.f, 0.f);
                if (grow < N_NODES) rA[it] = *(const float4*)&x[(size_t)grow * 256 + kb + g * 4];
                rB[it] = *(const uint4*)&g_w1hl[(size_t)((c + 1) * 256 + cn + row) * 64 + g * 8];
            }
        }

        // ---- MMAs on chunk c ----
#pragma unroll
        for (int ks = 0; ks < 2; ks++) {
            uint32_t ah[2][4], al[2][4], bh[4][4], bl[4][4];
#pragma unroll
            for (int m = 0; m < 2; m++) {
                int row = wr * 32 + m * 16 + raA;
                uint32_t hiAddr = sA + (row * G1_LDS + ks * 16 + kaA) * 2;
                ldsm4(ah[m], hiAddr);
                ldsm4(al[m], hiAddr + 64);
            }
#pragma unroll
            for (int nf2 = 0; nf2 < 4; nf2++) {
                int n = wc * 64 + nf2 * 16 + nB;
                uint32_t hiAddr = sB + (n * G1_LDS + ks * 16 + kB) * 2;
                ldsm4(bh[nf2], hiAddr);
                ldsm4(bl[nf2], hiAddr + 64);
            }
#pragma unroll
            for (int m = 0; m < 2; m++)
#pragma unroll
                for (int nf = 0; nf < 8; nf++) {
                    const uint32_t* b0h = &bh[nf >> 1][(nf & 1) * 2];
                    const uint32_t* b0l = &bl[nf >> 1][(nf & 1) * 2];
                    mma_bf16(acc[m][nf], ah[m], b0h);   // hi*hi
                    mma_bf16(acc[m][nf], ah[m], b0l);   // hi*lo
                    mma_bf16(acc[m][nf], al[m], b0h);   // lo*hi
                }
        }
        __syncthreads();
    }

    // ---- epilogue: store h1 (bf16) + fused per-head attention dots ----
    int h = (cn >> 6) + wc;                      // this warp's head (64 cols)
    float ps[2][2] = {{0.f, 0.f}, {0.f, 0.f}};
    float pd[2][2] = {{0.f, 0.f}, {0.f, 0.f}};
#pragma unroll
    for (int m = 0; m < 2; m++) {
        int r0 = tile0 + wr * 32 + m * 16 + (lane >> 2);
#pragma unroll
        for (int nf = 0; nf < 8; nf++) {
            int col = cn + wc * 64 + nf * 8 + (lane & 3) * 2;
            float v0 = acc[m][nf][0], v1 = acc[m][nf][1];
            float v2 = acc[m][nf][2], v3 = acc[m][nf][3];
            if (r0 < N_NODES)
                *(uint32_t*)&g_h1b[(size_t)r0 * 256 + col] = pack_bf16x2(v0, v1);
            if (r0 + 8 < N_NODES)
                *(uint32_t*)&g_h1b[(size_t)(r0 + 8) * 256 + col] = pack_bf16x2(v2, v3);
            ps[m][0] += v0 * sS[col] + v1 * sS[col + 1];
            pd[m][0] += v0 * sD[col] + v1 * sD[col + 1];
            ps[m][1] += v2 * sS[col] + v3 * sS[col + 1];
            pd[m][1] += v2 * sD[col] + v3 * sD[col + 1];
        }
    }
#pragma unroll
    for (int m = 0; m < 2; m++)
#pragma unroll
        for (int hf = 0; hf < 2; hf++) {
            float s = ps[m][hf], d = pd[m][hf];
            s += __shfl_xor_sync(0xffffffffu, s, 1); s += __shfl_xor_sync(0xffffffffu, s, 2);
            d += __shfl_xor_sync(0xffffffffu, d, 1); d += __shfl_xor_sync(0xffffffffu, d, 2);
            if ((lane & 3) == 0) {
                int r = tile0 + wr * 32 + m * 16 + hf * 8 + (lane >> 2);
                if (r < N_NODES) { g_asrc1[r * 4 + h] = s; g_adst1[r * 4 + h] = d; }
            }
        }
}

// ============================================================================
// GAT layer-1 softmax + aggregation + FUSED GEMM2 + layer-2 logits.
// Lane owns 8 CONTIGUOUS channels [lane*8, lane*8+8) = one head (lane>>3).
// ============================================================================
__global__ __launch_bounds__(256)
void agg1_fused_kernel(const float* __restrict__ b1, const float* __restrict__ W2,
                       const float* __restrict__ aS2, const float* __restrict__ aD2) {
    __shared__ float wt[256 * 16];   // W2 row-major [k][c]
    __shared__ float sv[8][256];
    __shared__ float sb1[256];
    int t = threadIdx.x;
    for (int i = t; i < 4096; i += 256) wt[i] = W2[i];
    sb1[t] = b1[t];
    __syncthreads();

    int w = t >> 5, lane = t & 31;
    int n = blockIdx.x * 8 + w;
    if (n >= N_NODES) return;
    int hd = lane >> 3;                          // this lane's head
    float advh = g_adst1[n * 4 + hd];
    int s0 = g_off[n], s1 = g_off[n + 1];

    float acc[8] = {0.f, 0.f, 0.f, 0.f, 0.f, 0.f, 0.f, 0.f};
    float denom = 0.f;
    for (int i = s0; i < s1; i++) {
        int src = g_csr[i];
        float as = __ldg(&g_asrc1[src * 4 + hd]);
        float e = as + advh;
        e = e > 0.f ? e : 0.2f * e;
        float wgt = __expf(e);
        denom += wgt;
        uint4 u = __ldg((const uint4*)(g_h1b + (size_t)src * 256 + lane * 8));
        const uint32_t uu[4] = {u.x, u.y, u.z, u.w};
#pragma unroll
        for (int j = 0; j < 4; j++) {
            __nv_bfloat162 bv = *(const __nv_bfloat162*)&uu[j];
            float2 f = __bfloat1622float2(bv);
            acc[2 * j]     += wgt * f.x;
            acc[2 * j + 1] += wgt * f.y;
        }
    }
    float inv = 1.f / (denom + 1e-16f);
#pragma unroll
    for (int j = 0; j < 8; j++) {
        int ch = lane * 8 + j;
        sv[w][ch] = fmaxf(acc[j] * inv + sb1[ch], 0.f);
    }
    __syncwarp();

    // fused GEMM2: h2[c] = sum_k v[k] * W2[k][c]
    int c = lane & 15, par = lane >> 4;
    float sum = 0.f;
#pragma unroll 4
    for (int kk = 0; kk < 128; kk++) {
        int k = 2 * kk + par;
        sum += sv[w][k] * wt[k * 16 + c];
    }
    sum += __shfl_xor_sync(0xffffffffu, sum, 16);
    if (lane < 16) g_h2[n * 16 + lane] = sum;
    float aS = (lane < 16) ? aS2[c] : 0.f;
    float aD = (lane < 16) ? aD2[c] : 0.f;
    float ss = warp_sum((lane < 16) ? sum * aS : 0.f);
    float sd = warp_sum((lane < 16) ? sum * aD : 0.f);
    if (lane == 0) { g_asrc2[n] = ss; g_adst2[n] = sd; }
}

// ---------------- GAT layer-2 + log_softmax (warp per dst node) -------------
// Half-warp edge parallelism: lanes 0-15 even edges, 16-31 odd edges;
// halves combined with one shfl_xor(16) before the softmax epilogue.
__global__ void agg2_kernel(const float* __restrict__ b2, float* __restrict__ out) {
    int t = threadIdx.x;
    int n = blockIdx.x * 8 + (t >> 5);
    int lane = t & 31;
    if (n >= N_NODES) return;
    float adv = g_adst2[n];
    int s0 = g_off[n], s1 = g_off[n + 1];
    int half = lane >> 4;       // 0 or 1
    int c = lane & 15;

    float acc = 0.f, denom = 0.f;
    for (int i = s0 + half; i < s1; i += 2) {
        int src = g_csr[i];
        float e = g_asrc2[src] + adv;
        e = e > 0.f ? e : 0.2f * e;
        float w = __expf(e);
        denom += w;
        acc += w * __ldg(&g_h2[src * 16 + c]);
    }
    // combine the two halves
    denom += __shfl_xor_sync(0xffffffffu, denom, 16);
    acc   += __shfl_xor_sync(0xffffffffu, acc, 16);

    float o = acc / (denom + 1e-16f) + ((lane < 16) ? b2[c] : 0.f);
    float v = (lane < 16) ? o : -1e30f;
    float mx = warp_max(v);
    float ex = (lane < 16) ? __expf(o - mx) : 0.f;
    float ssum = warp_sum(ex);
    if (lane < 16) out[(size_t)n * 16 + lane] = o - mx - logf(ssum);
}

// ---------------- launch ----------------
extern "C" void kernel_launch(void* const* d_in, const int* in_sizes, int n_in,
                              void* d_out, int out_size) {
    const float* x  = nullptr;
    const void*  ei = nullptr;
    const float* W1 = nullptr;
    const float* W2 = nullptr;
    const float* f256[3] = {nullptr, nullptr, nullptr};
    const float* f16[3]  = {nullptr, nullptr, nullptr};
    int c256 = 0, c16 = 0;
    for (int i = 0; i < n_in; i++) {
        int s = in_sizes[i];
        if (s == N_NODES * 256)      x  = (const float*)d_in[i];
        else if (s == 2 * E_RAW)     ei = d_in[i];
        else if (s == 256 * 256)     W1 = (const float*)d_in[i];
        else if (s == 256 * 16)      W2 = (const float*)d_in[i];
        else if (s == 256 && c256 < 3) f256[c256++] = (const float*)d_in[i];
        else if (s == 16  && c16  < 3) f16[c16++]   = (const float*)d_in[i];
    }
    const float* aS1 = f256[0];
    const float* aD1 = f256[1];
    const float* b1  = f256[2];
    const float* aS2 = f16[0];
    const float* aD2 = f16[1];
    const float* b2  = f16[2];
    float* out = (float*)d_out;

    // Fork: CSR build on side stream, concurrent with w1cvt+GEMM1 on main.
    cudaEventRecord(g_evFork, 0);
    cudaStreamWaitEvent(g_s2, g_evFork, 0);

    detect_init_kernel<<<SCAN_BLOCKS, 256, 0, g_s2>>>(ei);
    count_kernel<<<(E_RAW + 255) / 256, 256, 0, g_s2>>>(ei);
    scan1_kernel<<<SCAN_BLOCKS, 256, 0, g_s2>>>();
    scan2_kernel<<<1, 256, 0, g_s2>>>();
    scan3_kernel<<<SCAN_BLOCKS, 256, 0, g_s2>>>();
    scatter_kernel<<<(E_RAW + N_NODES + 255) / 256, 256, 0, g_s2>>>(ei);
    cudaEventRecord(g_evJoin, g_s2);

    w1cvt_kernel<<<8, 256>>>(W1);
    gemm1_mma_kernel<<<dim3(2, 392), 256>>>(x, aS1, aD1);

    cudaStreamWaitEvent(0, g_evJoin, 0);
    agg1_fused_kernel<<<(N_NODES + 7) / 8, 256>>>(b1, W2, aS2, aD2);
    agg2_kernel<<<(N_NODES + 7) / 8, 256>>>(b2, out);
}

// round 17
// speedup vs baseline: 1.0681x; 1.0681x over previous
#include <cuda_runtime.h>
#include <cuda_bf16.h>
#include <math.h>
#include <stdint.h>

#define N_NODES 50000
#define E_RAW   800000
#define E_TOT   (E_RAW + N_NODES)
#define SCAN_BLOCKS 196   // 196*256 = 50176 >= 50000

// ---------------- scratch (device globals; no allocation in kernel_launch) ----
__device__ __align__(16) __nv_bfloat16 g_h1b[N_NODES * 256];   // x @ W1 (bf16)
__device__ __align__(16) __nv_bfloat16 g_w1hl[8 * 256 * 64];   // W1 split, chunk-major
__device__ __align__(16) float g_asrc1[N_NODES * 4];
__device__ __align__(16) float g_adst1[N_NODES * 4];
__device__ __align__(16) float g_h2[N_NODES * 16];
__device__ float g_asrc2[N_NODES];
__device__ float g_adst2[N_NODES];
__device__ int   g_deg[N_NODES];
__device__ int   g_off[N_NODES + 1];
__device__ int   g_cur[N_NODES];
__device__ int   g_csr[E_TOT];
__device__ int   g_is64;
__device__ int   g_bsum[SCAN_BLOCKS];
__device__ int   g_boff[SCAN_BLOCKS];

// ---------------- host-side stream/events for capture-time fork/join --------
static cudaStream_t g_s2;
static cudaEvent_t  g_evFork, g_evJoin;
namespace {
struct _StreamInit {
    _StreamInit() {
        cudaStreamCreateWithFlags(&g_s2, cudaStreamNonBlocking);
        cudaEventCreateWithFlags(&g_evFork, cudaEventDisableTiming);
        cudaEventCreateWithFlags(&g_evJoin, cudaEventDisableTiming);
    }
};
_StreamInit _stream_init;
}

// ---------------- warp reductions ----------------
__device__ __forceinline__ float warp_max(float v) {
#pragma unroll
    for (int o = 16; o > 0; o >>= 1) v = fmaxf(v, __shfl_xor_sync(0xffffffffu, v, o));
    return v;
}
__device__ __forceinline__ float warp_sum(float v) {
#pragma unroll
    for (int o = 16; o > 0; o >>= 1) v += __shfl_xor_sync(0xffffffffu, v, o);
    return v;
}

// ---------------- detect edge dtype + init degrees (merged) ----------------
__global__ void detect_init_kernel(const void* __restrict__ eiv) {
    __shared__ int bad;
    int i = blockIdx.x * 256 + threadIdx.x;
    if (i < N_NODES) g_deg[i] = 1;  // self loop
    if (blockIdx.x == 0) {
        if (threadIdx.x == 0) bad = 0;
        __syncthreads();
        const long long* p = (const long long*)eiv;
        long long v = p[threadIdx.x];
        if (v < 0 || v >= (long long)N_NODES) atomicOr(&bad, 1);
        __syncthreads();
        if (threadIdx.x == 0) g_is64 = bad ? 0 : 1;
    }
}

__device__ __forceinline__ int load_edge(const void* eiv, int idx, int is64) {
    if (is64) return (int)((const long long*)eiv)[idx];
    return ((const int*)eiv)[idx];
}

// ---------------- CSR build ----------------
__global__ void count_kernel(const void* __restrict__ eiv) {
    int i = blockIdx.x * blockDim.x + threadIdx.x;
    if (i < E_RAW) {
        int dst = load_edge(eiv, E_RAW + i, g_is64);
        if ((unsigned)dst < (unsigned)N_NODES) atomicAdd(&g_deg[dst], 1);
    }
}

__global__ void scan1_kernel() {
    __shared__ int wsum[8];
    int idx = blockIdx.x * 256 + threadIdx.x;
    int d = (idx < N_NODES) ? g_deg[idx] : 0;
    int lane = threadIdx.x & 31, wid = threadIdx.x >> 5;
#pragma unroll
    for (int o = 16; o > 0; o >>= 1) d += __shfl_xor_sync(0xffffffffu, d, o);
    if (lane == 0) wsum[wid] = d;
    __syncthreads();
    if (threadIdx.x == 0) {
        int s = 0;
#pragma unroll
        for (int w = 0; w < 8; w++) s += wsum[w];
        g_bsum[blockIdx.x] = s;
    }
}

__global__ void scan2_kernel() {
    __shared__ int woff[8];
    int t = threadIdx.x;
    int v = (t < SCAN_BLOCKS) ? g_bsum[t] : 0;
    int lane = t & 31, wid = t >> 5;
    int s = v;
#pragma unroll
    for (int o = 1; o < 32; o <<= 1) {
        int u = __shfl_up_sync(0xffffffffu, s, o);
        if (lane >= o) s += u;
    }
    if (lane == 31) woff[wid] = s;
    __syncthreads();
    if (t == 0) {
        int run = 0;
#pragma unroll
        for (int w = 0; w < 8; w++) { int x = woff[w]; woff[w] = run; run += x; }
    }
    __syncthreads();
    int excl = s - v + woff[wid];
    if (t < SCAN_BLOCKS) g_boff[t] = excl;
    if (t == SCAN_BLOCKS - 1) g_off[N_NODES] = excl + v;
}

__global__ void scan3_kernel() {
    __shared__ int woff[8];
    int idx = blockIdx.x * 256 + threadIdx.x;
    int v = (idx < N_NODES) ? g_deg[idx] : 0;
    int lane = threadIdx.x & 31, wid = threadIdx.x >> 5;
    int s = v;
#pragma unroll
    for (int o = 1; o < 32; o <<= 1) {
        int u = __shfl_up_sync(0xffffffffu, s, o);
        if (lane >= o) s += u;
    }
    if (lane == 31) woff[wid] = s;
    __syncthreads();
    if (threadIdx.x == 0) {
        int run = 0;
#pragma unroll
        for (int w = 0; w < 8; w++) { int x = woff[w]; woff[w] = run; run += x; }
    }
    __syncthreads();
    int off = s - v + woff[wid] + g_boff[blockIdx.x];
    if (idx < N_NODES) { g_off[idx] = off; g_cur[idx] = off; }
}

__global__ void scatter_kernel(const void* __restrict__ eiv) {
    int i = blockIdx.x * blockDim.x + threadIdx.x;
    if (i < E_RAW) {
        int is64 = g_is64;
        int src = load_edge(eiv, i, is64);
        int dst = load_edge(eiv, E_RAW + i, is64);
        if ((unsigned)src < (unsigned)N_NODES && (unsigned)dst < (unsigned)N_NODES) {
            int pos = atomicAdd(&g_cur[dst], 1);
            if ((unsigned)pos < (unsigned)E_TOT) g_csr[pos] = src;
        }
    } else if (i < E_RAW + N_NODES) {
        int nn = i - E_RAW;
        int pos = atomicAdd(&g_cur[nn], 1);
        if ((unsigned)pos < (unsigned)E_TOT) g_csr[pos] = nn;
    }
}

// ---------------- bf16 helpers ----------------
__device__ __forceinline__ uint32_t pack_bf16x2(float a, float b) {
    __nv_bfloat16 ah = __float2bfloat16(a), bh = __float2bfloat16(b);
    return (uint32_t)__bfloat16_as_ushort(ah) | ((uint32_t)__bfloat16_as_ushort(bh) << 16);
}

// ---------------- pre-convert W1 only: [chunk][n][hi32|lo32] ----------------
__global__ void w1cvt_kernel(const float* __restrict__ W) {
    int idx = blockIdx.x * 256 + threadIdx.x;
    if (idx >= 2048) return;
    int c = idx >> 8, n = idx & 255;
    uint32_t hp[16], lp[16];
#pragma unroll
    for (int j = 0; j < 16; j++) {
        float a = W[(size_t)(c * 32 + 2 * j) * 256 + n];
        float b = W[(size_t)(c * 32 + 2 * j + 1) * 256 + n];
        hp[j] = pack_bf16x2(a, b);
        float la = a - __bfloat162float(__float2bfloat16(a));
        float lb = b - __bfloat162float(__float2bfloat16(b));
        lp[j] = pack_bf16x2(la, lb);
    }
    __nv_bfloat16* dst = g_w1hl + (size_t)(c * 256 + n) * 64;
#pragma unroll
    for (int q = 0; q < 4; q++) {
        *(uint4*)(dst + q * 8)      = make_uint4(hp[4 * q], hp[4 * q + 1], hp[4 * q + 2], hp[4 * q + 3]);
        *(uint4*)(dst + 32 + q * 8) = make_uint4(lp[4 * q], lp[4 * q + 1], lp[4 * q + 2], lp[4 * q + 3]);
    }
}

// ============================================================================
// GEMM1 via warp-level mma.sync (bf16 split). A staged by in-kernel split;
// B copied from pre-split g_w1hl. 2 CTAs/SM for cross-CTA phase overlap.
// ============================================================================
#define G1_LDS 72   // smem row stride in bf16

__device__ __forceinline__ uint32_t smem_u32(const void* p) {
    uint32_t a;
    asm("{ .reg .u64 t; cvta.to.shared.u64 t, %1; cvt.u32.u64 %0, t; }" : "=r"(a) : "l"(p));
    return a;
}
__device__ __forceinline__ void ldsm4(uint32_t* r, uint32_t addr) {
    asm volatile("ldmatrix.sync.aligned.m8n8.x4.shared.b16 {%0,%1,%2,%3}, [%4];"
                 : "=r"(r[0]), "=r"(r[1]), "=r"(r[2]), "=r"(r[3]) : "r"(addr));
}
__device__ __forceinline__ void mma_bf16(float* d, const uint32_t* a, const uint32_t* b) {
    asm volatile(
        "mma.sync.aligned.m16n8k16.row.col.f32.bf16.bf16.f32 "
        "{%0,%1,%2,%3}, {%4,%5,%6,%7}, {%8,%9}, {%0,%1,%2,%3};"
        : "+f"(d[0]), "+f"(d[1]), "+f"(d[2]), "+f"(d[3])
        : "r"(a[0]), "r"(a[1]), "r"(a[2]), "r"(a[3]), "r"(b[0]), "r"(b[1]));
}

__global__ __launch_bounds__(256, 2)
void gemm1_mma_kernel(const float* __restrict__ x,
                      const float* __restrict__ attS, const float* __restrict__ attD) {
    __shared__ __align__(16) __nv_bfloat16 As[128 * G1_LDS];
    __shared__ __align__(16) __nv_bfloat16 Bs[128 * G1_LDS];
    __shared__ float sS[256], sD[256];

    int tid = threadIdx.x, wid = tid >> 5, lane = tid & 31;
    int wr = wid >> 1, wc = wid & 1;          // warp grid 4x2
    int tile0 = blockIdx.y * 128;             // row base
    int cn = blockIdx.x * 128;                // col base
    sS[tid] = attS[tid];
    sD[tid] = attD[tid];

    float acc[2][8][4];
#pragma unroll
    for (int m = 0; m < 2; m++)
#pragma unroll
        for (int nf = 0; nf < 8; nf++)
#pragma unroll
            for (int j = 0; j < 4; j++) acc[m][nf][j] = 0.f;

    uint32_t sA = smem_u32(As), sB = smem_u32(Bs);
    int raA = lane & 15, kaA = (lane >> 4) * 8;                 // A: x4 = m16 x k16
    int nB = (lane & 7) | ((lane >> 4) << 3);                   // B: x4 = n16 x k16
    int kB = (lane & 8) ? 8 : 0;

    for (int c = 0; c < 8; c++) {
        int kb = c * 32;
        // ---- stage A: 128 rows x 32 k (fp32 -> bf16 hi|lo split, in-kernel) ----
#pragma unroll
        for (int it = 0; it < 4; it++) {
            int idx = tid + it * 256;
            int row = idx >> 3, g = idx & 7;
            int grow = tile0 + row;
            float4 v = make_float4(0.f, 0.f, 0.f, 0.f);
            if (grow < N_NODES) v = *(const float4*)&x[(size_t)grow * 256 + kb + g * 4];
            uint32_t hi0 = pack_bf16x2(v.x, v.y), hi1 = pack_bf16x2(v.z, v.w);
            float l0 = v.x - __bfloat162float(__float2bfloat16(v.x));
            float l1 = v.y - __bfloat162float(__float2bfloat16(v.y));
            float l2 = v.z - __bfloat162float(__float2bfloat16(v.z));
            float l3 = v.w - __bfloat162float(__float2bfloat16(v.w));
            uint32_t lo0 = pack_bf16x2(l0, l1), lo1 = pack_bf16x2(l2, l3);
            *(uint2*)&As[row * G1_LDS + g * 4]      = make_uint2(hi0, hi1);
            *(uint2*)&As[row * G1_LDS + 32 + g * 4] = make_uint2(lo0, lo1);
        }
        // ---- stage B: pure uint4 copies from pre-split W1 ----
#pragma unroll
        for (int it = 0; it < 4; it++) {
            int idx = tid + it * 256;
            int nl = idx >> 3, q = idx & 7;
            *(uint4*)&Bs[nl * G1_LDS + q * 8] =
                *(const uint4*)&g_w1hl[(size_t)(c * 256 + cn + nl) * 64 + q * 8];
        }
        __syncthreads();

#pragma unroll
        for (int ks = 0; ks < 2; ks++) {
            uint32_t ah[2][4], al[2][4], bh[4][4], bl[4][4];
#pragma unroll
            for (int m = 0; m < 2; m++) {
                int row = wr * 32 + m * 16 + raA;
                uint32_t hiAddr = sA + (row * G1_LDS + ks * 16 + kaA) * 2;
                ldsm4(ah[m], hiAddr);
                ldsm4(al[m], hiAddr + 64);
            }
#pragma unroll
            for (int nf2 = 0; nf2 < 4; nf2++) {
                int n = wc * 64 + nf2 * 16 + nB;
                uint32_t hiAddr = sB + (n * G1_LDS + ks * 16 + kB) * 2;
                ldsm4(bh[nf2], hiAddr);
                ldsm4(bl[nf2], hiAddr + 64);
            }
#pragma unroll
            for (int m = 0; m < 2; m++)
#pragma unroll
                for (int nf = 0; nf < 8; nf++) {
                    const uint32_t* b0h = &bh[nf >> 1][(nf & 1) * 2];
                    const uint32_t* b0l = &bl[nf >> 1][(nf & 1) * 2];
                    mma_bf16(acc[m][nf], ah[m], b0h);   // hi*hi
                    mma_bf16(acc[m][nf], ah[m], b0l);   // hi*lo
                    mma_bf16(acc[m][nf], al[m], b0h);   // lo*hi
                }
        }
        __syncthreads();
    }

    // ---- epilogue: store h1 (bf16) + fused per-head attention dots ----
    int h = (cn >> 6) + wc;                      // this warp's head (64 cols)
    float ps[2][2] = {{0.f, 0.f}, {0.f, 0.f}};
    float pd[2][2] = {{0.f, 0.f}, {0.f, 0.f}};
#pragma unroll
    for (int m = 0; m < 2; m++) {
        int r0 = tile0 + wr * 32 + m * 16 + (lane >> 2);
#pragma unroll
        for (int nf = 0; nf < 8; nf++) {
            int col = cn + wc * 64 + nf * 8 + (lane & 3) * 2;
            float v0 = acc[m][nf][0], v1 = acc[m][nf][1];
            float v2 = acc[m][nf][2], v3 = acc[m][nf][3];
            if (r0 < N_NODES)
                *(uint32_t*)&g_h1b[(size_t)r0 * 256 + col] = pack_bf16x2(v0, v1);
            if (r0 + 8 < N_NODES)
                *(uint32_t*)&g_h1b[(size_t)(r0 + 8) * 256 + col] = pack_bf16x2(v2, v3);
            ps[m][0] += v0 * sS[col] + v1 * sS[col + 1];
            pd[m][0] += v0 * sD[col] + v1 * sD[col + 1];
            ps[m][1] += v2 * sS[col] + v3 * sS[col + 1];
            pd[m][1] += v2 * sD[col] + v3 * sD[col + 1];
        }
    }
#pragma unroll
    for (int m = 0; m < 2; m++)
#pragma unroll
        for (int hf = 0; hf < 2; hf++) {
            float s = ps[m][hf], d = pd[m][hf];
            s += __shfl_xor_sync(0xffffffffu, s, 1); s += __shfl_xor_sync(0xffffffffu, s, 2);
            d += __shfl_xor_sync(0xffffffffu, d, 1); d += __shfl_xor_sync(0xffffffffu, d, 2);
            if ((lane & 3) == 0) {
                int r = tile0 + wr * 32 + m * 16 + hf * 8 + (lane >> 2);
                if (r < N_NODES) { g_asrc1[r * 4 + h] = s; g_adst1[r * 4 + h] = d; }
            }
        }
}

// ============================================================================
// GAT layer-1 softmax + aggregation + FUSED GEMM2 + layer-2 logits.
// Lane owns 8 CONTIGUOUS channels [lane*8, lane*8+8) = one head (lane>>3).
// ============================================================================
__global__ __launch_bounds__(256)
void agg1_fused_kernel(const float* __restrict__ b1, const float* __restrict__ W2,
                       const float* __restrict__ aS2, const float* __restrict__ aD2) {
    __shared__ float wt[256 * 16];   // W2 row-major [k][c]
    __shared__ float sv[8][256];
    __shared__ float sb1[256];
    int t = threadIdx.x;
    for (int i = t; i < 4096; i += 256) wt[i] = W2[i];
    sb1[t] = b1[t];
    __syncthreads();

    int w = t >> 5, lane = t & 31;
    int n = blockIdx.x * 8 + w;
    if (n >= N_NODES) return;
    int hd = lane >> 3;                          // this lane's head
    float advh = g_adst1[n * 4 + hd];
    int s0 = g_off[n], s1 = g_off[n + 1];

    float acc[8] = {0.f, 0.f, 0.f, 0.f, 0.f, 0.f, 0.f, 0.f};
    float denom = 0.f;
    for (int i = s0; i < s1; i++) {
        int src = g_csr[i];
        float as = __ldg(&g_asrc1[src * 4 + hd]);
        float e = as + advh;
        e = e > 0.f ? e : 0.2f * e;
        float wgt = __expf(e);
        denom += wgt;
        uint4 u = __ldg((const uint4*)(g_h1b + (size_t)src * 256 + lane * 8));
        const uint32_t uu[4] = {u.x, u.y, u.z, u.w};
#pragma unroll
        for (int j = 0; j < 4; j++) {
            __nv_bfloat162 bv = *(const __nv_bfloat162*)&uu[j];
            float2 f = __bfloat1622float2(bv);
            acc[2 * j]     += wgt * f.x;
            acc[2 * j + 1] += wgt * f.y;
        }
    }
    float inv = 1.f / (denom + 1e-16f);
#pragma unroll
    for (int j = 0; j < 8; j++) {
        int ch = lane * 8 + j;
        sv[w][ch] = fmaxf(acc[j] * inv + sb1[ch], 0.f);
    }
    __syncwarp();

    // fused GEMM2: h2[c] = sum_k v[k] * W2[k][c]
    int c = lane & 15, par = lane >> 4;
    float sum = 0.f;
#pragma unroll 4
    for (int kk = 0; kk < 128; kk++) {
        int k = 2 * kk + par;
        sum += sv[w][k] * wt[k * 16 + c];
    }
    sum += __shfl_xor_sync(0xffffffffu, sum, 16);
    if (lane < 16) g_h2[n * 16 + lane] = sum;
    float aS = (lane < 16) ? aS2[c] : 0.f;
    float aD = (lane < 16) ? aD2[c] : 0.f;
    float ss = warp_sum((lane < 16) ? sum * aS : 0.f);
    float sd = warp_sum((lane < 16) ? sum * aD : 0.f);
    if (lane == 0) { g_asrc2[n] = ss; g_adst2[n] = sd; }
}

// ---------------- GAT layer-2 + log_softmax (warp per dst node) -------------
// Half-warp edge parallelism: lanes 0-15 even edges, 16-31 odd edges.
__global__ void agg2_kernel(const float* __restrict__ b2, float* __restrict__ out) {
    int t = threadIdx.x;
    int n = blockIdx.x * 8 + (t >> 5);
    int lane = t & 31;
    if (n >= N_NODES) return;
    float adv = g_adst2[n];
    int s0 = g_off[n], s1 = g_off[n + 1];
    int half = lane >> 4;       // 0 or 1
    int c = lane & 15;

    float acc = 0.f, denom = 0.f;
    for (int i = s0 + half; i < s1; i += 2) {
        int src = g_csr[i];
        float e = g_asrc2[src] + adv;
        e = e > 0.f ? e : 0.2f * e;
        float w = __expf(e);
        denom += w;
        acc += w * __ldg(&g_h2[src * 16 + c]);
    }
    denom += __shfl_xor_sync(0xffffffffu, denom, 16);
    acc   += __shfl_xor_sync(0xffffffffu, acc, 16);

    float o = acc / (denom + 1e-16f) + ((lane < 16) ? b2[c] : 0.f);
    float v = (lane < 16) ? o : -1e30f;
    float mx = warp_max(v);
    float ex = (lane < 16) ? __expf(o - mx) : 0.f;
    float ssum = warp_sum(ex);
    if (lane < 16) out[(size_t)n * 16 + lane] = o - mx - logf(ssum);
}

// ---------------- launch ----------------
extern "C" void kernel_launch(void* const* d_in, const int* in_sizes, int n_in,
                              void* d_out, int out_size) {
    const float* x  = nullptr;
    const void*  ei = nullptr;
    const float* W1 = nullptr;
    const float* W2 = nullptr;
    const float* f256[3] = {nullptr, nullptr, nullptr};
    const float* f16[3]  = {nullptr, nullptr, nullptr};
    int c256 = 0, c16 = 0;
    for (int i = 0; i < n_in; i++) {
        int s = in_sizes[i];
        if (s == N_NODES * 256)      x  = (const float*)d_in[i];
        else if (s == 2 * E_RAW)     ei = d_in[i];
        else if (s == 256 * 256)     W1 = (const float*)d_in[i];
        else if (s == 256 * 16)      W2 = (const float*)d_in[i];
        else if (s == 256 && c256 < 3) f256[c256++] = (const float*)d_in[i];
        else if (s == 16  && c16  < 3) f16[c16++]   = (const float*)d_in[i];
    }
    const float* aS1 = f256[0];
    const float* aD1 = f256[1];
    const float* b1  = f256[2];
    const float* aS2 = f16[0];
    const float* aD2 = f16[1];
    const float* b2  = f16[2];
    float* out = (float*)d_out;

    // Fork: CSR build on side stream, concurrent with w1cvt+GEMM1 on main.
    cudaEventRecord(g_evFork, 0);
    cudaStreamWaitEvent(g_s2, g_evFork, 0);

    detect_init_kernel<<<SCAN_BLOCKS, 256, 0, g_s2>>>(ei);
    count_kernel<<<(E_RAW + 255) / 256, 256, 0, g_s2>>>(ei);
    scan1_kernel<<<SCAN_BLOCKS, 256, 0, g_s2>>>();
    scan2_kernel<<<1, 256, 0, g_s2>>>();
    scan3_kernel<<<SCAN_BLOCKS, 256, 0, g_s2>>>();
    scatter_kernel<<<(E_RAW + N_NODES + 255) / 256, 256, 0, g_s2>>>(ei);
    cudaEventRecord(g_evJoin, g_s2);

    w1cvt_kernel<<<8, 256>>>(W1);
    gemm1_mma_kernel<<<dim3(2, 392), 256>>>(x, aS1, aD1);

    cudaStreamWaitEvent(0, g_evJoin, 0);
    agg1_fused_kernel<<<(N_NODES + 7) / 8, 256>>>(b1, W2, aS2, aD2);
    agg2_kernel<<<(N_NODES + 7) / 8, 256>>>(b2, out);
}